// round 10
// baseline (speedup 1.0000x reference)
#include <cuda_runtime.h>
#include <cuda_bf16.h>
#include <math.h>
#include <stdint.h>

// ---------------- problem constants ----------------
#define BATCH 512
#define T_IN 64
#define IN_DIM 16
#define HS 32
#define OUT_DIM 32
#define H 960
#define G3 2880
#define T_PRED 48

#define NC_H 15             // h-pass K-chunks (960/64)
#define MTILE 128
#define NTILE 96            // 3 gates x 32 units
#define NTHR 256
#define NCTA 120
#define NJOBS (2 * T_IN + 3 * T_PRED)   // 272

// ---------------- smem layout ----------------
// [0..768)        sbias (192 floats)
// [1024..52224)   Mp plane 128x100 fp32
// [52224..70656)  Np plane 128x36 fp32
// [70656..192512) 2-stage ring
#define MSTRIDE 100
#define N2STRIDE 36
#define PLANE_M 1024
#define PLANE_N 52224
#define RING_OFF 70656
#define ROWB 272
#define ABYTES (MTILE * ROWB)      // 34816
#define BBYTES (NTILE * ROWB)      // 26112
#define STAGE (ABYTES + BBYTES)    // 60928
#define SMEM_BYTES (RING_OFF + 2 * STAGE)   // 192512

// ---------------- device scratch ----------------
#define WBIG (G3 * NC_H * 64)
#define WSM  (G3 * 64)
#define HSN  (NC_H * BATCH * 64)

__device__ float g_W[6][WBIG];      // tf32: eWhh0,eWih1,eWhh1,dWhh0,dWih1,dWhh1
__device__ float g_Wsm[2][WSM];     // eWih0, dWih0
__device__ float g_h0f[2][BATCH * H];
__device__ float g_h1f[2][BATCH * H];
__device__ float g_h0a[2][HSN];
__device__ float g_h1a[2][HSN];
__device__ float g_xin[T_IN * BATCH * 64];
__device__ float g_ll[BATCH * 64];
__device__ float g_xd[BATCH * 64];
__device__ int   g_bar[NJOBS];

// ---------------- helpers ----------------
__device__ __forceinline__ uint32_t smem_u32(const void* p) {
    uint32_t a;
    asm("{ .reg .u64 t; cvta.to.shared.u64 t, %1; cvt.u32.u64 %0, t; }" : "=r"(a) : "l"(p));
    return a;
}
__device__ __forceinline__ void cp16(uint32_t dst, const void* src) {
    asm volatile("cp.async.cg.shared.global [%0], [%1], 16;" :: "r"(dst), "l"(src) : "memory");
}
#define CP_COMMIT() asm volatile("cp.async.commit_group;" ::: "memory")
#define CP_WAIT0()  asm volatile("cp.async.wait_group 0;" ::: "memory")

__device__ __forceinline__ uint32_t lds32(uint32_t a) {
    uint32_t v;
    asm volatile("ld.shared.b32 %0, [%1];" : "=r"(v) : "r"(a));
    return v;
}
__device__ __forceinline__ void mma_tf32(float (&d)[4], const uint32_t (&a)[4],
                                         uint32_t b0, uint32_t b1) {
    asm volatile(
        "mma.sync.aligned.m16n8k8.row.col.f32.tf32.tf32.f32 "
        "{%0,%1,%2,%3}, {%4,%5,%6,%7}, {%8,%9}, {%0,%1,%2,%3};"
        : "+f"(d[0]), "+f"(d[1]), "+f"(d[2]), "+f"(d[3])
        : "r"(a[0]), "r"(a[1]), "r"(a[2]), "r"(a[3]), "r"(b0), "r"(b1));
}
__device__ __forceinline__ float tf32r(float v) {
    uint32_t o;
    asm("cvt.rna.tf32.f32 %0, %1;" : "=r"(o) : "f"(v));
    return __uint_as_float(o);
}
__device__ __forceinline__ float sigf(float v) { return 1.0f / (1.0f + expf(-v)); }

__device__ __forceinline__ void job_wait(int* bar, int dep) {
    if (dep >= 0) {
        while (((volatile int*)bar)[dep] < NCTA) { __nanosleep(32); }
        __threadfence();
    }
}
__device__ __forceinline__ void job_arrive(int* bar, int jid) {
    __threadfence();
    __syncthreads();
    if (threadIdx.x == 0) atomicAdd(&bar[jid], 1);
}

// ---------------- one GRU step job (all 120 CTAs) ----------------
__device__ __noinline__ void do_gru(
    const float* xA, int ncx, const float* hA,
    const float* w1, const float* w2,
    const float* bih, const float* bhh,
    const float* hprevf, float* houtf, float* hAout,
    float* hcat, int hcat_ld,
    int* bar, int jid, int hdep, int xdep)
{
    extern __shared__ char smem[];
    float* sbias = (float*)smem;
    float* Mp = (float*)(smem + PLANE_M);
    float* Np = (float*)(smem + PLANE_N);
    const uint32_t sb = smem_u32(smem);
    const uint32_t ring = sb + RING_OFF;

    const int tid  = threadIdx.x;
    const int lane = tid & 31;
    const int w    = tid >> 5;
    const int wm   = w & 3;
    const int wn   = w >> 2;
    const int bid  = blockIdx.x;
    const int ub   = bid % 30;
    const int m0   = (bid / 30) * MTILE;
    const int nc   = NC_H + ncx;

    if (tid < 192) {
        int g = (tid < 96) ? (tid >> 5) : ((tid - 96) >> 5);
        int j = tid & 31;
        sbias[tid] = (tid < 96) ? bih[g * H + ub * 32 + j] : bhh[g * H + ub * 32 + j];
    }

    float acc[2][6][4];
    float accn[2][4][4];
#pragma unroll
    for (int m2 = 0; m2 < 2; ++m2) {
#pragma unroll
        for (int f = 0; f < 6; ++f)
#pragma unroll
            for (int i = 0; i < 4; ++i) acc[m2][f][i] = 0.f;
#pragma unroll
        for (int f = 0; f < 4; ++f)
#pragma unroll
            for (int i = 0; i < 4; ++i) accn[m2][f][i] = 0.f;
    }

    const uint32_t aoff = (uint32_t)(wm * 32 + (lane >> 2)) * ROWB + (lane & 3) * 4;
    const uint32_t boff = ABYTES + (uint32_t)(wn * 48 + (lane >> 2)) * ROWB + (lane & 3) * 4;

    auto issue_load = [&](int c) {
        if (c == 0)    job_wait(bar, hdep);
        if (c == NC_H) job_wait(bar, xdep);
        const float* ap = (c < NC_H) ? (hA + ((size_t)c * BATCH + m0) * 64)
                                     : (xA + ((size_t)(c - NC_H) * BATCH + m0) * 64);
        const float* bp = (c < NC_H) ? (w2 + ((size_t)c * G3 + ub * NTILE) * 64)
                                     : (w1 + ((size_t)(c - NC_H) * G3 + ub * NTILE) * 64);
        const char* asrc = (const char*)ap;
        const char* bsrc = (const char*)bp;
        uint32_t d = ring + (uint32_t)(c & 1) * STAGE;
#pragma unroll
        for (int i = 0; i < 8; ++i) {              // A: 2048 x 16B
            int u = tid + i * NTHR;
            cp16(d + (u >> 4) * ROWB + (u & 15) * 16, asrc + (size_t)u * 16);
        }
#pragma unroll
        for (int i = 0; i < 6; ++i) {              // B: 1536 x 16B
            int u = tid + i * NTHR;
            cp16(d + ABYTES + (u >> 4) * ROWB + (u & 15) * 16, bsrc + (size_t)u * 16);
        }
        CP_COMMIT();
    };

#define CHUNK_BODY(SPLIT)                                                       \
    {                                                                           \
        _Pragma("unroll")                                                       \
        for (int kk = 0; kk < 8; ++kk) {                                        \
            uint32_t a[2][4];                                                   \
            _Pragma("unroll")                                                   \
            for (int mb = 0; mb < 2; ++mb) {                                    \
                uint32_t ab = stage + aoff + mb * (16 * ROWB) + kk * 32;        \
                a[mb][0] = lds32(ab);                                           \
                a[mb][1] = lds32(ab + 8 * ROWB);                                \
                a[mb][2] = lds32(ab + 16);                                      \
                a[mb][3] = lds32(ab + 8 * ROWB + 16);                           \
            }                                                                   \
            _Pragma("unroll")                                                   \
            for (int nb = 0; nb < 6; ++nb) {                                    \
                uint32_t bb = stage + boff + nb * (8 * ROWB) + kk * 32;         \
                uint32_t b0 = lds32(bb), b1 = lds32(bb + 16);                   \
                if (SPLIT && nb >= 2) {                                         \
                    mma_tf32(accn[0][nb - 2], a[0], b0, b1);                    \
                    mma_tf32(accn[1][nb - 2], a[1], b0, b1);                    \
                } else {                                                        \
                    mma_tf32(acc[0][nb], a[0], b0, b1);                         \
                    mma_tf32(acc[1][nb], a[1], b0, b1);                         \
                }                                                               \
            }                                                                   \
        }                                                                       \
    }

    // double-buffer mainloop: wait(0) -> sync -> issue(c+1) -> consume(c)
    issue_load(0);
    for (int c = 0; c < nc; ++c) {
        CP_WAIT0();
        __syncthreads();
        if (c + 1 < nc) issue_load(c + 1);
        const uint32_t stage = ring + (uint32_t)(c & 1) * STAGE;
        if (c < NC_H && wn == 1) CHUNK_BODY(1) else CHUNK_BODY(0)
    }
#undef CHUNK_BODY

    // epilogue: planes -> gate math -> stores
    {
        const int rb = wm * 32 + (lane >> 2);
        const int cb = wn * 48 + (lane & 3) * 2;
#pragma unroll
        for (int m2 = 0; m2 < 2; ++m2)
#pragma unroll
            for (int f = 0; f < 6; ++f) {
                int r = rb + m2 * 16;
                int cc = cb + f * 8;
                *(float2*)&Mp[r * MSTRIDE + cc]       = make_float2(acc[m2][f][0], acc[m2][f][1]);
                *(float2*)&Mp[(r + 8) * MSTRIDE + cc] = make_float2(acc[m2][f][2], acc[m2][f][3]);
            }
        if (wn == 1) {
            const int cb2 = (lane & 3) * 2;
#pragma unroll
            for (int m2 = 0; m2 < 2; ++m2)
#pragma unroll
                for (int f = 0; f < 4; ++f) {
                    int r = rb + m2 * 16;
                    int cc = cb2 + f * 8;
                    *(float2*)&Np[r * N2STRIDE + cc]       = make_float2(accn[m2][f][0], accn[m2][f][1]);
                    *(float2*)&Np[(r + 8) * N2STRIDE + cc] = make_float2(accn[m2][f][2], accn[m2][f][3]);
                }
        }
    }
    __syncthreads();

    {
        const int row = tid >> 1;
        const int j0  = (tid & 1) * 16;
        const int brow = m0 + row;
        const int cj = ub >> 1;
        const int kb = (ub & 1) * 32;

        float hv[16];
#pragma unroll
        for (int v = 0; v < 8; ++v) {
            int j = j0 + v * 2;
            float2 R  = *(float2*)&Mp[row * MSTRIDE + j];
            float2 Z  = *(float2*)&Mp[row * MSTRIDE + 32 + j];
            float2 NX = *(float2*)&Mp[row * MSTRIDE + 64 + j];
            float2 NH = *(float2*)&Np[row * N2STRIDE + j];
            float2 HP = *(const float2*)(hprevf + (size_t)brow * H + ub * 32 + j);
#pragma unroll
            for (int e = 0; e < 2; ++e) {
                int jj = j + e;
                float rr = sigf(((e ? R.y : R.x))  + sbias[jj]      + sbias[96 + jj]);
                float zz = sigf(((e ? Z.y : Z.x))  + sbias[32 + jj] + sbias[128 + jj]);
                float nn = tanhf(((e ? NX.y : NX.x)) + sbias[64 + jj]
                                 + rr * (((e ? NH.y : NH.x)) + sbias[160 + jj]));
                hv[j - j0 + e] = (1.0f - zz) * nn + zz * (e ? HP.y : HP.x);
            }
        }
        const size_t ob = (size_t)brow * H + ub * 32 + j0;
#pragma unroll
        for (int q = 0; q < 4; ++q)
            *(float4*)(houtf + ob + q * 4) = make_float4(hv[q*4], hv[q*4+1], hv[q*4+2], hv[q*4+3]);
        if (hcat) {
            const size_t cbo = (size_t)brow * hcat_ld + ub * 32 + j0;
#pragma unroll
            for (int q = 0; q < 4; ++q)
                *(float4*)(hcat + cbo + q * 4) = make_float4(hv[q*4], hv[q*4+1], hv[q*4+2], hv[q*4+3]);
        }
        const size_t so = ((size_t)cj * BATCH + brow) * 64 + kb + j0;
#pragma unroll
        for (int q = 0; q < 4; ++q)
            *(float4*)(hAout + so + q * 4) = make_float4(tf32r(hv[q*4]), tf32r(hv[q*4+1]),
                                                         tf32r(hv[q*4+2]), tf32r(hv[q*4+3]));
    }
    job_arrive(bar, jid);
}

// ---------------- linear job (64 CTAs compute, rest pass through) ----------------
__device__ __noinline__ void do_linear(
    const float* h, const float* W, const float* bias,
    float* out, int out_ld, float* xdA,
    int* bar, int jid, int dep)
{
    job_wait(bar, dep);
    const int bid = blockIdx.x;
    if (bid < 64) {
        extern __shared__ char smem[];
        float (*Ws)[33] = (float(*)[33])(smem + PLANE_M);
        float (*hs)[64] = (float(*)[64])(smem + PLANE_M + 64 * 33 * 4);
        const int tid = threadIdx.x;
        const int o = tid & 31;
        const int bl = tid >> 5;
        const int b0 = bid * 8;

        float acc = 0.f;
        for (int k0 = 0; k0 < H; k0 += 64) {
#pragma unroll
            for (int i = 0; i < 8; ++i) {
                int idx = tid + i * 256;
                Ws[idx & 63][idx >> 6] = W[(size_t)(idx >> 6) * H + k0 + (idx & 63)];
            }
#pragma unroll
            for (int i = 0; i < 2; ++i) {
                int idx = tid + i * 256;
                hs[idx >> 6][idx & 63] = h[(size_t)(b0 + (idx >> 6)) * H + k0 + (idx & 63)];
            }
            __syncthreads();
#pragma unroll
            for (int kk = 0; kk < 64; ++kk)
                acc = fmaf(hs[bl][kk], Ws[kk][o], acc);
            __syncthreads();
        }
        float v = acc + bias[o];
        int b = b0 + bl;
        out[(size_t)b * out_ld + o] = v;
        xdA[(size_t)b * 64 + o] = tf32r(v);
    }
    job_arrive(bar, jid);
}

// ---------------- persistent megakernel ----------------
struct P {
    const float *xin, *xll; float *xd;
    const float *Wsm0, *Wsm1;
    const float *Wb0, *Wb1, *Wb2, *Wb3, *Wb4, *Wb5;
    const float *ebih0, *ebhh0, *ebih1, *ebhh1;
    const float *dbih0, *dbhh0, *dbih1, *dbhh1;
    float *h0f0, *h0f1, *h1f0, *h1f1;
    float *h0a0, *h0a1, *h1a0, *h1a1;
    const float *linW, *linb;
    float *outputs, *hidden;
    int *bar;
};

__global__ __launch_bounds__(NTHR, 1) void seq2seq_persist(P p)
{
    float* h0f[2] = { p.h0f0, p.h0f1 };
    float* h1f[2] = { p.h1f0, p.h1f1 };
    float* h0a[2] = { p.h0a0, p.h0a1 };
    float* h1a[2] = { p.h1a0, p.h1a1 };
    const int out_ld = T_PRED * OUT_DIM;
    const int hid_ld = T_PRED * 2 * H;

    int jid = 0;
    for (int t = 0; t < T_IN; ++t) {
        do_gru(p.xin + (size_t)t * BATCH * 64, 1, h0a[t & 1],
               p.Wsm0, p.Wb0, p.ebih0, p.ebhh0,
               h0f[t & 1], h0f[(t + 1) & 1], h0a[(t + 1) & 1],
               nullptr, 0, p.bar, jid, (jid >= 2) ? jid - 2 : -1, -1);
        ++jid;
        do_gru(h0a[(t + 1) & 1], NC_H, h1a[t & 1],
               p.Wb1, p.Wb2, p.ebih1, p.ebhh1,
               h1f[t & 1], h1f[(t + 1) & 1], h1a[(t + 1) & 1],
               nullptr, 0, p.bar, jid, (jid >= 2) ? jid - 2 : -1, jid - 1);
        ++jid;
    }
    for (int u = 0; u < T_PRED; ++u) {
        const int s = T_IN + u;
        do_gru((u == 0) ? p.xll : p.xd, 1, h0a[s & 1],
               p.Wsm1, p.Wb3, p.dbih0, p.dbhh0,
               h0f[s & 1], h0f[(s + 1) & 1], h0a[(s + 1) & 1],
               p.hidden + (size_t)u * 2 * H, hid_ld,
               p.bar, jid, (u == 0) ? jid - 2 : jid - 3, (u == 0) ? -1 : jid - 1);
        ++jid;
        do_gru(h0a[(s + 1) & 1], NC_H, h1a[s & 1],
               p.Wb4, p.Wb5, p.dbih1, p.dbhh1,
               h1f[s & 1], h1f[(s + 1) & 1], h1a[(s + 1) & 1],
               p.hidden + (size_t)u * 2 * H + H, hid_ld,
               p.bar, jid, (u == 0) ? jid - 2 : jid - 3, jid - 1);
        ++jid;
        do_linear(h1f[(s + 1) & 1], p.linW, p.linb,
                  p.outputs + (size_t)u * OUT_DIM, out_ld, p.xd,
                  p.bar, jid, jid - 1);
        ++jid;
    }
}

// ---------------- prep kernels ----------------
__global__ void prep_weight_big(const float* __restrict__ W, float* __restrict__ Wt)
{
    int total = G3 * NC_H * 64;
    for (int idx = blockIdx.x * blockDim.x + threadIdx.x; idx < total; idx += gridDim.x * blockDim.x) {
        int k = idx & 63;
        int q = idx >> 6;
        int n = q % G3;
        int c = q / G3;
        int ubl = n / 96, rem = n % 96, g = rem >> 5, jj = rem & 31;
        int row = g * H + ubl * 32 + jj;
        int col = c * 64 + k;
        Wt[idx] = tf32r(W[(size_t)row * H + col]);
    }
}

__global__ void prep_weight_sm(const float* __restrict__ W, int K, float* __restrict__ Wt)
{
    int total = G3 * 64;
    for (int idx = blockIdx.x * blockDim.x + threadIdx.x; idx < total; idx += gridDim.x * blockDim.x) {
        int k = idx & 63;
        int n = idx >> 6;
        int ubl = n / 96, rem = n % 96, g = rem >> 5, jj = rem & 31;
        int row = g * H + ubl * 32 + jj;
        float v = (k < K) ? W[(size_t)row * K + k] : 0.f;
        Wt[idx] = tf32r(v);
    }
}

__global__ void prep_in(const float* __restrict__ in_data, float* __restrict__ A)
{
    int total = T_IN * BATCH * 64;
    for (int idx = blockIdx.x * blockDim.x + threadIdx.x; idx < total; idx += gridDim.x * blockDim.x) {
        int k = idx & 63;
        int q = idx >> 6;
        int b = q & (BATCH - 1);
        int t = q >> 9;
        float v = (k < IN_DIM) ? in_data[((size_t)b * T_IN + t) * IN_DIM + k] : 0.f;
        A[idx] = tf32r(v);
    }
}

__global__ void prep_ll(const float* __restrict__ ll_src, float* __restrict__ A)
{
    int total = BATCH * 64;
    for (int idx = blockIdx.x * blockDim.x + threadIdx.x; idx < total; idx += gridDim.x * blockDim.x) {
        int k = idx & 63;
        int b = idx >> 6;
        float v = (k < HS) ? ll_src[(size_t)b * HS + k] : 0.f;
        A[idx] = tf32r(v);
    }
}

// ---------------- host ----------------
extern "C" void kernel_launch(void* const* d_in, const int* in_sizes, int n_in,
                              void* d_out, int out_size)
{
    const float* in_data  = (const float*)d_in[0];
    const float* last_loc = (const float*)d_in[1];
    const float* eWih0 = (const float*)d_in[3];
    const float* eWhh0 = (const float*)d_in[4];
    const float* ebih0 = (const float*)d_in[5];
    const float* ebhh0 = (const float*)d_in[6];
    const float* eWih1 = (const float*)d_in[7];
    const float* eWhh1 = (const float*)d_in[8];
    const float* ebih1 = (const float*)d_in[9];
    const float* ebhh1 = (const float*)d_in[10];
    const float* dWih0 = (const float*)d_in[11];
    const float* dWhh0 = (const float*)d_in[12];
    const float* dbih0 = (const float*)d_in[13];
    const float* dbhh0 = (const float*)d_in[14];
    const float* dWih1 = (const float*)d_in[15];
    const float* dWhh1 = (const float*)d_in[16];
    const float* dbih1 = (const float*)d_in[17];
    const float* dbhh1 = (const float*)d_in[18];
    const float* linW  = (const float*)d_in[19];
    const float* linb  = (const float*)d_in[20];

    float* outputs = (float*)d_out;
    float* hidden  = (float*)d_out + (size_t)BATCH * T_PRED * OUT_DIM;

    float (*Wb)[WBIG];          cudaGetSymbolAddress((void**)&Wb, g_W);
    float (*Wsm)[WSM];          cudaGetSymbolAddress((void**)&Wsm, g_Wsm);
    float (*h0f)[BATCH * H];    cudaGetSymbolAddress((void**)&h0f, g_h0f);
    float (*h1f)[BATCH * H];    cudaGetSymbolAddress((void**)&h1f, g_h1f);
    float (*h0a)[HSN];          cudaGetSymbolAddress((void**)&h0a, g_h0a);
    float (*h1a)[HSN];          cudaGetSymbolAddress((void**)&h1a, g_h1a);
    float* xin = nullptr;       cudaGetSymbolAddress((void**)&xin, g_xin);
    float* xll = nullptr;       cudaGetSymbolAddress((void**)&xll, g_ll);
    float* xd  = nullptr;       cudaGetSymbolAddress((void**)&xd, g_xd);
    int*   bar = nullptr;       cudaGetSymbolAddress((void**)&bar, g_bar);

    cudaFuncSetAttribute(seq2seq_persist, cudaFuncAttributeMaxDynamicSharedMemorySize, SMEM_BYTES);

    prep_weight_big<<<1024, 256>>>(eWhh0, Wb[0]);
    prep_weight_big<<<1024, 256>>>(eWih1, Wb[1]);
    prep_weight_big<<<1024, 256>>>(eWhh1, Wb[2]);
    prep_weight_big<<<1024, 256>>>(dWhh0, Wb[3]);
    prep_weight_big<<<1024, 256>>>(dWih1, Wb[4]);
    prep_weight_big<<<1024, 256>>>(dWhh1, Wb[5]);
    prep_weight_sm<<<256, 256>>>(eWih0, IN_DIM, Wsm[0]);
    prep_weight_sm<<<256, 256>>>(dWih0, HS,     Wsm[1]);
    prep_in<<<512, 256>>>(in_data, xin);
    prep_ll<<<64, 256>>>(last_loc, xll);

    cudaMemsetAsync(h0f[0], 0, (size_t)BATCH * H * sizeof(float));
    cudaMemsetAsync(h1f[0], 0, (size_t)BATCH * H * sizeof(float));
    cudaMemsetAsync(h0a[0], 0, (size_t)HSN * sizeof(float));
    cudaMemsetAsync(h1a[0], 0, (size_t)HSN * sizeof(float));
    cudaMemsetAsync(bar,    0, NJOBS * sizeof(int));

    P p;
    p.xin = xin; p.xll = xll; p.xd = xd;
    p.Wsm0 = Wsm[0]; p.Wsm1 = Wsm[1];
    p.Wb0 = Wb[0]; p.Wb1 = Wb[1]; p.Wb2 = Wb[2];
    p.Wb3 = Wb[3]; p.Wb4 = Wb[4]; p.Wb5 = Wb[5];
    p.ebih0 = ebih0; p.ebhh0 = ebhh0; p.ebih1 = ebih1; p.ebhh1 = ebhh1;
    p.dbih0 = dbih0; p.dbhh0 = dbhh0; p.dbih1 = dbih1; p.dbhh1 = dbhh1;
    p.h0f0 = h0f[0]; p.h0f1 = h0f[1]; p.h1f0 = h1f[0]; p.h1f1 = h1f[1];
    p.h0a0 = h0a[0]; p.h0a1 = h0a[1]; p.h1a0 = h1a[0]; p.h1a1 = h1a[1];
    p.linW = linW; p.linb = linb;
    p.outputs = outputs; p.hidden = hidden;
    p.bar = bar;

    seq2seq_persist<<<NCTA, NTHR, SMEM_BYTES>>>(p);
}

// round 11
// speedup vs baseline: 1.5691x; 1.5691x over previous
#include <cuda_runtime.h>
#include <cuda_fp16.h>
#include <math.h>
#include <stdint.h>

// ---------------- problem constants ----------------
#define BATCH 512
#define T_IN 64
#define IN_DIM 16
#define HS 32
#define OUT_DIM 32
#define H 960
#define G3 2880
#define T_PRED 48

#define NC_H 15             // 960/64 K-chunks
#define MTILE 128
#define NTILE 96            // 3 gates x 32 units
#define NTHR 256

// smem: [bias 1024B][3 stages]; fp16 rows: 64 elems (128B) + 16B pad = 144B
#define ROWB 144
#define ABYTES (MTILE * ROWB)      // 18432
#define BBYTES (NTILE * ROWB)      // 13824
#define STAGE (ABYTES + BBYTES)    // 32256
#define SMEM_BYTES (1024 + 3 * STAGE)   // 97792
// epilogue planes (alias stage ring after final sync)
#define MSTRIDE 100
#define N2STRIDE 36
#define N2OFF 51200

// ---------------- device scratch ----------------
#define WBIG (G3 * NC_H * 64)
#define WSM  (G3 * 64)
#define HSN  (NC_H * BATCH * 64)

__device__ __half g_W[6][WBIG];      // fp16: eWhh0,eWih1,eWhh1,dWhh0,dWih1,dWhh1
__device__ __half g_Wsm[2][WSM];     // eWih0, dWih0
__device__ float  g_h0f[2][BATCH * H];
__device__ float  g_h1f[2][BATCH * H];
__device__ __half g_h0a[2][HSN];     // fp16 A-planes (ping-pong)
__device__ __half g_h1a[2][HSN];
__device__ __half g_xin[T_IN * BATCH * 64];
__device__ __half g_ll[BATCH * 64];
__device__ __half g_xd[BATCH * 64];

// ---------------- helpers ----------------
__device__ __forceinline__ uint32_t smem_u32(const void* p) {
    uint32_t a;
    asm("{ .reg .u64 t; cvta.to.shared.u64 t, %1; cvt.u32.u64 %0, t; }" : "=r"(a) : "l"(p));
    return a;
}
__device__ __forceinline__ void cp16(uint32_t dst, const void* src) {
    asm volatile("cp.async.cg.shared.global [%0], [%1], 16;" :: "r"(dst), "l"(src) : "memory");
}
#define CP_COMMIT() asm volatile("cp.async.commit_group;" ::: "memory")
#define CP_WAIT(n)  asm volatile("cp.async.wait_group %0;" :: "n"(n) : "memory")

__device__ __forceinline__ void ldm4(uint32_t (&r)[4], uint32_t a) {
    asm volatile("ldmatrix.sync.aligned.m8n8.x4.shared.b16 {%0,%1,%2,%3}, [%4];"
        : "=r"(r[0]), "=r"(r[1]), "=r"(r[2]), "=r"(r[3]) : "r"(a));
}
__device__ __forceinline__ void mma_f16(float (&d)[4], const uint32_t (&a)[4],
                                        uint32_t b0, uint32_t b1) {
    asm volatile(
        "mma.sync.aligned.m16n8k16.row.col.f32.f16.f16.f32 "
        "{%0,%1,%2,%3}, {%4,%5,%6,%7}, {%8,%9}, {%0,%1,%2,%3};"
        : "+f"(d[0]), "+f"(d[1]), "+f"(d[2]), "+f"(d[3])
        : "r"(a[0]), "r"(a[1]), "r"(a[2]), "r"(a[3]), "r"(b0), "r"(b1));
}
__device__ __forceinline__ float sigf(float v) { return 1.0f / (1.0f + expf(-v)); }

// ---------------- fused GRU step (fp16 mma, single pass) ----------------
__global__ __launch_bounds__(NTHR, 1)
void gru_step_h(const __half* __restrict__ xA, int ncx,
                const __half* __restrict__ hA,
                const __half* __restrict__ w1, const __half* __restrict__ w2,
                const float* __restrict__ bih, const float* __restrict__ bhh,
                const float* __restrict__ hprevf, float* __restrict__ houtf,
                __half* __restrict__ hAout,
                float* __restrict__ hcat, int hcat_ld)
{
    extern __shared__ char smem[];
    float* sbias = (float*)smem;
    const uint32_t sb = smem_u32(smem);

    const int tid  = threadIdx.x;
    const int lane = tid & 31;
    const int w    = tid >> 5;
    const int wm   = w & 3;      // m-block (32 rows)
    const int wn   = w >> 2;     // n-half (48 cols)
    const int m0   = blockIdx.x * MTILE;
    const int ub   = blockIdx.y;
    const int nc   = ncx + NC_H;

    if (tid < 192) {
        int g = (tid < 96) ? (tid >> 5) : ((tid - 96) >> 5);
        int j = tid & 31;
        sbias[tid] = (tid < 96) ? bih[g * H + ub * 32 + j] : bhh[g * H + ub * 32 + j];
    }

    // acc = r/z (both passes) + n-gate x-pass; accn = n-gate h-pass (wn==1 only)
    float acc[2][6][4];
    float accn[2][4][4];
#pragma unroll
    for (int m2 = 0; m2 < 2; ++m2) {
#pragma unroll
        for (int f = 0; f < 6; ++f)
#pragma unroll
            for (int i = 0; i < 4; ++i) acc[m2][f][i] = 0.f;
#pragma unroll
        for (int f = 0; f < 4; ++f)
#pragma unroll
            for (int i = 0; i < 4; ++i) accn[m2][f][i] = 0.f;
    }

    // ldmatrix lane offsets (within stage)
    const int lrow = (lane & 7) + ((lane >> 3) & 1) * 8;
    const int lcol = (lane >> 4) * 16;
    const uint32_t aoff = (uint32_t)(wm * 32 + lrow) * ROWB + lcol;
    const uint32_t boff = ABYTES + (uint32_t)(wn * 48 + lrow) * ROWB + lcol;

    auto issue_load = [&](int c) {
        const __half* ap = (c < ncx) ? (xA + ((size_t)c * BATCH + m0) * 64)
                                     : (hA + ((size_t)(c - ncx) * BATCH + m0) * 64);
        const __half* bp = (c < ncx) ? (w1 + ((size_t)c * G3 + ub * NTILE) * 64)
                                     : (w2 + ((size_t)(c - ncx) * G3 + ub * NTILE) * 64);
        const char* asrc = (const char*)ap;
        const char* bsrc = (const char*)bp;
        uint32_t d = sb + 1024 + (uint32_t)(c % 3) * STAGE;
#pragma unroll
        for (int i = 0; i < 4; ++i) {              // A: 1024 x 16B
            int u = tid + i * NTHR;
            cp16(d + (u >> 3) * ROWB + (u & 7) * 16, asrc + (size_t)u * 16);
        }
#pragma unroll
        for (int i = 0; i < 3; ++i) {              // B: 768 x 16B
            int u = tid + i * NTHR;
            cp16(d + ABYTES + (u >> 3) * ROWB + (u & 7) * 16, bsrc + (size_t)u * 16);
        }
        CP_COMMIT();
    };

    issue_load(0); issue_load(1);

#define CHUNK_BODY(SPLIT)                                                       \
    {                                                                           \
        _Pragma("unroll")                                                       \
        for (int kk = 0; kk < 4; ++kk) {                                        \
            uint32_t a0[4], a1[4], b0[4], b1[4], b2[4];                         \
            ldm4(a0, stage + aoff + kk * 32);                                   \
            ldm4(a1, stage + aoff + 16 * ROWB + kk * 32);                       \
            ldm4(b0, stage + boff + kk * 32);                                   \
            ldm4(b1, stage + boff + 16 * ROWB + kk * 32);                       \
            ldm4(b2, stage + boff + 32 * ROWB + kk * 32);                       \
            mma_f16(acc[0][0], a0, b0[0], b0[2]);                               \
            mma_f16(acc[1][0], a1, b0[0], b0[2]);                               \
            mma_f16(acc[0][1], a0, b0[1], b0[3]);                               \
            mma_f16(acc[1][1], a1, b0[1], b0[3]);                               \
            if (SPLIT) {                                                        \
                mma_f16(accn[0][0], a0, b1[0], b1[2]);                          \
                mma_f16(accn[1][0], a1, b1[0], b1[2]);                          \
                mma_f16(accn[0][1], a0, b1[1], b1[3]);                          \
                mma_f16(accn[1][1], a1, b1[1], b1[3]);                          \
                mma_f16(accn[0][2], a0, b2[0], b2[2]);                          \
                mma_f16(accn[1][2], a1, b2[0], b2[2]);                          \
                mma_f16(accn[0][3], a0, b2[1], b2[3]);                          \
                mma_f16(accn[1][3], a1, b2[1], b2[3]);                          \
            } else {                                                            \
                mma_f16(acc[0][2], a0, b1[0], b1[2]);                           \
                mma_f16(acc[1][2], a1, b1[0], b1[2]);                           \
                mma_f16(acc[0][3], a0, b1[1], b1[3]);                           \
                mma_f16(acc[1][3], a1, b1[1], b1[3]);                           \
                mma_f16(acc[0][4], a0, b2[0], b2[2]);                           \
                mma_f16(acc[1][4], a1, b2[0], b2[2]);                           \
                mma_f16(acc[0][5], a0, b2[1], b2[3]);                           \
                mma_f16(acc[1][5], a1, b2[1], b2[3]);                           \
            }                                                                   \
        }                                                                       \
    }

    // single-sync multistage mainloop: per-thread wait -> barrier -> prefetch -> consume
    for (int c = 0; c < nc; ++c) {
        if (c + 1 < nc) { CP_WAIT(1); } else { CP_WAIT(0); }
        __syncthreads();
        if (c + 2 < nc) issue_load(c + 2);
        const uint32_t stage = sb + 1024 + (uint32_t)(c % 3) * STAGE;
        if (c >= ncx && wn == 1) CHUNK_BODY(1) else CHUNK_BODY(0)
    }
#undef CHUNK_BODY
    __syncthreads();   // ring fully consumed before plane overwrite

    // ---------------- epilogue: accums -> smem planes -> gate math ----------------
    float* Mp = (float*)(smem + 1024);
    float* Np = (float*)(smem + 1024 + N2OFF);
    {
        const int rb = wm * 32 + (lane >> 2);
        const int cb = wn * 48 + (lane & 3) * 2;
#pragma unroll
        for (int m2 = 0; m2 < 2; ++m2) {
#pragma unroll
            for (int f = 0; f < 6; ++f) {
                int r = rb + m2 * 16;
                int cc = cb + f * 8;
                *(float2*)&Mp[r * MSTRIDE + cc]       = make_float2(acc[m2][f][0], acc[m2][f][1]);
                *(float2*)&Mp[(r + 8) * MSTRIDE + cc] = make_float2(acc[m2][f][2], acc[m2][f][3]);
            }
        }
        if (wn == 1) {
            const int cb2 = (lane & 3) * 2;
#pragma unroll
            for (int m2 = 0; m2 < 2; ++m2) {
#pragma unroll
                for (int f = 0; f < 4; ++f) {
                    int r = rb + m2 * 16;
                    int cc = cb2 + f * 8;
                    *(float2*)&Np[r * N2STRIDE + cc]       = make_float2(accn[m2][f][0], accn[m2][f][1]);
                    *(float2*)&Np[(r + 8) * N2STRIDE + cc] = make_float2(accn[m2][f][2], accn[m2][f][3]);
                }
            }
        }
    }
    __syncthreads();

    {
        const int row = tid >> 1;
        const int j0  = (tid & 1) * 16;
        const int brow = m0 + row;
        const int cj = ub >> 1;
        const int kb = (ub & 1) * 32;

        float hv[16];
#pragma unroll
        for (int v = 0; v < 8; ++v) {
            int j = j0 + v * 2;
            float2 R  = *(float2*)&Mp[row * MSTRIDE + j];
            float2 Z  = *(float2*)&Mp[row * MSTRIDE + 32 + j];
            float2 NX = *(float2*)&Mp[row * MSTRIDE + 64 + j];
            float2 NH = *(float2*)&Np[row * N2STRIDE + j];
            float2 HP = *(const float2*)(hprevf + (size_t)brow * H + ub * 32 + j);
#pragma unroll
            for (int e = 0; e < 2; ++e) {
                int jj = j + e;
                float rr = sigf(((e ? R.y : R.x))  + sbias[jj]      + sbias[96 + jj]);
                float zz = sigf(((e ? Z.y : Z.x))  + sbias[32 + jj] + sbias[128 + jj]);
                float nn = tanhf(((e ? NX.y : NX.x)) + sbias[64 + jj]
                                 + rr * (((e ? NH.y : NH.x)) + sbias[160 + jj]));
                hv[j - j0 + e] = (1.0f - zz) * nn + zz * (e ? HP.y : HP.x);
            }
        }
        const size_t ob = (size_t)brow * H + ub * 32 + j0;
#pragma unroll
        for (int q = 0; q < 4; ++q)
            *(float4*)(houtf + ob + q * 4) = make_float4(hv[q*4], hv[q*4+1], hv[q*4+2], hv[q*4+3]);
        if (hcat) {
            const size_t cbo = (size_t)brow * hcat_ld + ub * 32 + j0;
#pragma unroll
            for (int q = 0; q < 4; ++q)
                *(float4*)(hcat + cbo + q * 4) = make_float4(hv[q*4], hv[q*4+1], hv[q*4+2], hv[q*4+3]);
        }
        // fp16 A-plane for next step
        __half hh[16];
#pragma unroll
        for (int i = 0; i < 16; ++i) hh[i] = __float2half_rn(hv[i]);
        const size_t so = ((size_t)cj * BATCH + brow) * 64 + kb + j0;
        *(uint4*)(hAout + so)     = ((uint4*)hh)[0];
        *(uint4*)(hAout + so + 8) = ((uint4*)hh)[1];
    }
}

// ---------------- linear head ----------------
__global__ __launch_bounds__(256)
void linear_kernel(const float* __restrict__ h,
                   const float* __restrict__ W, const float* __restrict__ bias,
                   float* __restrict__ out, int out_ld,
                   __half* __restrict__ xdA)
{
    __shared__ float Ws[64][33];
    __shared__ float hs[8][64];
    const int tid = threadIdx.x;
    const int o = tid & 31;
    const int bl = tid >> 5;
    const int b0 = blockIdx.x * 8;

    float acc = 0.f;
    for (int k0 = 0; k0 < H; k0 += 64) {
#pragma unroll
        for (int i = 0; i < 8; ++i) {
            int idx = tid + i * 256;
            Ws[idx & 63][idx >> 6] = W[(size_t)(idx >> 6) * H + k0 + (idx & 63)];
        }
#pragma unroll
        for (int i = 0; i < 2; ++i) {
            int idx = tid + i * 256;
            hs[idx >> 6][idx & 63] = h[(size_t)(b0 + (idx >> 6)) * H + k0 + (idx & 63)];
        }
        __syncthreads();
#pragma unroll
        for (int kk = 0; kk < 64; ++kk)
            acc = fmaf(hs[bl][kk], Ws[kk][o], acc);
        __syncthreads();
    }
    float v = acc + bias[o];
    int b = b0 + bl;
    out[(size_t)b * out_ld + o] = v;
    xdA[(size_t)b * 64 + o] = __float2half_rn(v);
}

// ---------------- prep kernels ----------------
__global__ void prep_weight_big(const float* __restrict__ W, __half* __restrict__ Wt)
{
    int total = G3 * NC_H * 64;
    for (int idx = blockIdx.x * blockDim.x + threadIdx.x; idx < total; idx += gridDim.x * blockDim.x) {
        int k = idx & 63;
        int q = idx >> 6;
        int n = q % G3;
        int c = q / G3;
        int ubl = n / 96, rem = n % 96, g = rem >> 5, jj = rem & 31;
        int row = g * H + ubl * 32 + jj;
        int col = c * 64 + k;
        Wt[idx] = __float2half_rn(W[(size_t)row * H + col]);
    }
}

__global__ void prep_weight_sm(const float* __restrict__ W, int K, __half* __restrict__ Wt)
{
    int total = G3 * 64;
    for (int idx = blockIdx.x * blockDim.x + threadIdx.x; idx < total; idx += gridDim.x * blockDim.x) {
        int k = idx & 63;
        int n = idx >> 6;
        int ubl = n / 96, rem = n % 96, g = rem >> 5, jj = rem & 31;
        int row = g * H + ubl * 32 + jj;
        float v = (k < K) ? W[(size_t)row * K + k] : 0.f;
        Wt[idx] = __float2half_rn(v);
    }
}

__global__ void prep_in(const float* __restrict__ in_data, __half* __restrict__ A)
{
    int total = T_IN * BATCH * 64;
    for (int idx = blockIdx.x * blockDim.x + threadIdx.x; idx < total; idx += gridDim.x * blockDim.x) {
        int k = idx & 63;
        int q = idx >> 6;
        int b = q & (BATCH - 1);
        int t = q >> 9;
        float v = (k < IN_DIM) ? in_data[((size_t)b * T_IN + t) * IN_DIM + k] : 0.f;
        A[idx] = __float2half_rn(v);
    }
}

__global__ void prep_ll(const float* __restrict__ ll_src, __half* __restrict__ A)
{
    int total = BATCH * 64;
    for (int idx = blockIdx.x * blockDim.x + threadIdx.x; idx < total; idx += gridDim.x * blockDim.x) {
        int k = idx & 63;
        int b = idx >> 6;
        float v = (k < HS) ? ll_src[(size_t)b * HS + k] : 0.f;
        A[idx] = __float2half_rn(v);
    }
}

// ---------------- host ----------------
extern "C" void kernel_launch(void* const* d_in, const int* in_sizes, int n_in,
                              void* d_out, int out_size)
{
    const float* in_data  = (const float*)d_in[0];
    const float* last_loc = (const float*)d_in[1];
    const float* eWih0 = (const float*)d_in[3];
    const float* eWhh0 = (const float*)d_in[4];
    const float* ebih0 = (const float*)d_in[5];
    const float* ebhh0 = (const float*)d_in[6];
    const float* eWih1 = (const float*)d_in[7];
    const float* eWhh1 = (const float*)d_in[8];
    const float* ebih1 = (const float*)d_in[9];
    const float* ebhh1 = (const float*)d_in[10];
    const float* dWih0 = (const float*)d_in[11];
    const float* dWhh0 = (const float*)d_in[12];
    const float* dbih0 = (const float*)d_in[13];
    const float* dbhh0 = (const float*)d_in[14];
    const float* dWih1 = (const float*)d_in[15];
    const float* dWhh1 = (const float*)d_in[16];
    const float* dbih1 = (const float*)d_in[17];
    const float* dbhh1 = (const float*)d_in[18];
    const float* linW  = (const float*)d_in[19];
    const float* linb  = (const float*)d_in[20];

    float* outputs = (float*)d_out;
    float* hidden  = (float*)d_out + (size_t)BATCH * T_PRED * OUT_DIM;

    __half (*Wb)[WBIG];         cudaGetSymbolAddress((void**)&Wb, g_W);
    __half (*Wsm)[WSM];         cudaGetSymbolAddress((void**)&Wsm, g_Wsm);
    float (*h0f)[BATCH * H];    cudaGetSymbolAddress((void**)&h0f, g_h0f);
    float (*h1f)[BATCH * H];    cudaGetSymbolAddress((void**)&h1f, g_h1f);
    __half (*h0a)[HSN];         cudaGetSymbolAddress((void**)&h0a, g_h0a);
    __half (*h1a)[HSN];         cudaGetSymbolAddress((void**)&h1a, g_h1a);
    __half* xin = nullptr;      cudaGetSymbolAddress((void**)&xin, g_xin);
    __half* xll = nullptr;      cudaGetSymbolAddress((void**)&xll, g_ll);
    __half* xd  = nullptr;      cudaGetSymbolAddress((void**)&xd, g_xd);

    cudaFuncSetAttribute(gru_step_h, cudaFuncAttributeMaxDynamicSharedMemorySize, SMEM_BYTES);

    prep_weight_big<<<1024, 256>>>(eWhh0, Wb[0]);
    prep_weight_big<<<1024, 256>>>(eWih1, Wb[1]);
    prep_weight_big<<<1024, 256>>>(eWhh1, Wb[2]);
    prep_weight_big<<<1024, 256>>>(dWhh0, Wb[3]);
    prep_weight_big<<<1024, 256>>>(dWih1, Wb[4]);
    prep_weight_big<<<1024, 256>>>(dWhh1, Wb[5]);
    prep_weight_sm<<<256, 256>>>(eWih0, IN_DIM, Wsm[0]);
    prep_weight_sm<<<256, 256>>>(dWih0, HS,     Wsm[1]);
    prep_in<<<512, 256>>>(in_data, xin);
    prep_ll<<<64, 256>>>(last_loc, xll);

    cudaMemsetAsync(h0f[0], 0, (size_t)BATCH * H * sizeof(float));
    cudaMemsetAsync(h1f[0], 0, (size_t)BATCH * H * sizeof(float));
    cudaMemsetAsync(h0a[0], 0, (size_t)HSN * sizeof(__half));
    cudaMemsetAsync(h1a[0], 0, (size_t)HSN * sizeof(__half));
    cudaMemsetAsync(xd,     0, (size_t)BATCH * 64 * sizeof(__half));

    dim3 grid(BATCH / MTILE, H / 32);   // (4, 30)
    int p0 = 0, p1 = 0;
    const int out_ld = T_PRED * OUT_DIM;
    const int hid_ld = T_PRED * 2 * H;

    // ---- encoder ----
    for (int t = 0; t < T_IN; ++t) {
        gru_step_h<<<grid, NTHR, SMEM_BYTES>>>(
            xin + (size_t)t * BATCH * 64, 1,
            h0a[p0], Wsm[0], Wb[0],
            ebih0, ebhh0, h0f[p0], h0f[1 - p0], h0a[1 - p0],
            nullptr, 0);
        p0 ^= 1;
        gru_step_h<<<grid, NTHR, SMEM_BYTES>>>(
            h0a[p0], NC_H,
            h1a[p1], Wb[1], Wb[2],
            ebih1, ebhh1, h1f[p1], h1f[1 - p1], h1a[1 - p1],
            nullptr, 0);
        p1 ^= 1;
    }

    // ---- decoder ----
    for (int t = 0; t < T_PRED; ++t) {
        const __half* xAp = (t == 0) ? xll : xd;
        gru_step_h<<<grid, NTHR, SMEM_BYTES>>>(
            xAp, 1,
            h0a[p0], Wsm[1], Wb[3],
            dbih0, dbhh0, h0f[p0], h0f[1 - p0], h0a[1 - p0],
            hidden + (size_t)t * 2 * H, hid_ld);
        p0 ^= 1;
        gru_step_h<<<grid, NTHR, SMEM_BYTES>>>(
            h0a[p0], NC_H,
            h1a[p1], Wb[4], Wb[5],
            dbih1, dbhh1, h1f[p1], h1f[1 - p1], h1a[1 - p1],
            hidden + (size_t)t * 2 * H + H, hid_ld);
        p1 ^= 1;
        linear_kernel<<<BATCH / 8, 256>>>(h1f[p1], linW, linb,
                                          outputs + (size_t)t * OUT_DIM, out_ld, xd);
    }
}

// round 12
// speedup vs baseline: 1.5933x; 1.0154x over previous
#include <cuda_runtime.h>
#include <cuda_fp16.h>
#include <math.h>
#include <stdint.h>

// ---------------- problem constants ----------------
#define BATCH 512
#define T_IN 64
#define IN_DIM 16
#define HS 32
#define OUT_DIM 32
#define H 960
#define G3 2880
#define T_PRED 48

#define KC 160              // K-chunk (divides 960)
#define NCH 6               // h-pass chunks: 960/160
#define MTILE 128
#define NTILE 96            // 3 gates x 32 units
#define NTHR 256

// smem: [bias 1024B][2 stages]; fp16 rows: 160 elems (320B) + 16B pad = 336B
#define ROWB 336
#define ABYTES (MTILE * ROWB)      // 43008
#define BBYTES (NTILE * ROWB)      // 32256
#define STAGE (ABYTES + BBYTES)    // 75264
#define SMEM_BYTES (1024 + 2 * STAGE)   // 151552
// epilogue planes (alias stage ring after final sync)
#define MSTRIDE 100
#define N2STRIDE 36
#define N2OFF 51200

// ---------------- device scratch ----------------
#define WBIG (G3 * NCH * KC)       // 2880*6*160
#define WSM  (G3 * KC)
#define HSN  (NCH * BATCH * KC)    // 6*512*160

__device__ __half g_W[6][WBIG];      // fp16: eWhh0,eWih1,eWhh1,dWhh0,dWih1,dWhh1
__device__ __half g_Wsm[2][WSM];     // eWih0, dWih0 (K padded to 160)
__device__ float  g_h0f[2][BATCH * H];
__device__ float  g_h1f[2][BATCH * H];
__device__ __half g_h0a[2][HSN];     // fp16 A-planes (ping-pong)
__device__ __half g_h1a[2][HSN];
__device__ __half g_xin[T_IN * BATCH * KC];
__device__ __half g_ll[BATCH * KC];
__device__ __half g_xd[BATCH * KC];

// ---------------- helpers ----------------
__device__ __forceinline__ uint32_t smem_u32(const void* p) {
    uint32_t a;
    asm("{ .reg .u64 t; cvta.to.shared.u64 t, %1; cvt.u32.u64 %0, t; }" : "=r"(a) : "l"(p));
    return a;
}
__device__ __forceinline__ void cp16(uint32_t dst, const void* src) {
    asm volatile("cp.async.cg.shared.global [%0], [%1], 16;" :: "r"(dst), "l"(src) : "memory");
}
#define CP_COMMIT() asm volatile("cp.async.commit_group;" ::: "memory")
#define CP_WAIT0()  asm volatile("cp.async.wait_group 0;" ::: "memory")

__device__ __forceinline__ void ldm4(uint32_t (&r)[4], uint32_t a) {
    asm volatile("ldmatrix.sync.aligned.m8n8.x4.shared.b16 {%0,%1,%2,%3}, [%4];"
        : "=r"(r[0]), "=r"(r[1]), "=r"(r[2]), "=r"(r[3]) : "r"(a));
}
__device__ __forceinline__ void mma_f16(float (&d)[4], const uint32_t (&a)[4],
                                        uint32_t b0, uint32_t b1) {
    asm volatile(
        "mma.sync.aligned.m16n8k16.row.col.f32.f16.f16.f32 "
        "{%0,%1,%2,%3}, {%4,%5,%6,%7}, {%8,%9}, {%0,%1,%2,%3};"
        : "+f"(d[0]), "+f"(d[1]), "+f"(d[2]), "+f"(d[3])
        : "r"(a[0]), "r"(a[1]), "r"(a[2]), "r"(a[3]), "r"(b0), "r"(b1));
}
__device__ __forceinline__ float sigf(float v) { return 1.0f / (1.0f + expf(-v)); }

// ---------------- fused GRU step (fp16 mma, K=160 chunks, 2-stage) ----------------
__global__ __launch_bounds__(NTHR, 1)
void gru_step_h(const __half* __restrict__ xA, int ncx,
                const __half* __restrict__ hA,
                const __half* __restrict__ w1, const __half* __restrict__ w2,
                const float* __restrict__ bih, const float* __restrict__ bhh,
                const float* __restrict__ hprevf, float* __restrict__ houtf,
                __half* __restrict__ hAout,
                float* __restrict__ hcat, int hcat_ld)
{
    extern __shared__ char smem[];
    float* sbias = (float*)smem;
    const uint32_t sb = smem_u32(smem);

    const int tid  = threadIdx.x;
    const int lane = tid & 31;
    const int w    = tid >> 5;
    const int wm   = w & 3;      // m-block (32 rows)
    const int wn   = w >> 2;     // n-half (48 cols)
    const int m0   = blockIdx.x * MTILE;
    const int ub   = blockIdx.y;
    const int nc   = ncx + NCH;

    if (tid < 192) {
        int g = (tid < 96) ? (tid >> 5) : ((tid - 96) >> 5);
        int j = tid & 31;
        sbias[tid] = (tid < 96) ? bih[g * H + ub * 32 + j] : bhh[g * H + ub * 32 + j];
    }

    // acc = r/z (both passes) + n-gate x-pass; accn = n-gate h-pass (wn==1 only)
    float acc[2][6][4];
    float accn[2][4][4];
#pragma unroll
    for (int m2 = 0; m2 < 2; ++m2) {
#pragma unroll
        for (int f = 0; f < 6; ++f)
#pragma unroll
            for (int i = 0; i < 4; ++i) acc[m2][f][i] = 0.f;
#pragma unroll
        for (int f = 0; f < 4; ++f)
#pragma unroll
            for (int i = 0; i < 4; ++i) accn[m2][f][i] = 0.f;
    }

    // ldmatrix lane offsets (within stage)
    const int lrow = (lane & 7) + ((lane >> 3) & 1) * 8;
    const int lcol = (lane >> 4) * 16;
    const uint32_t aoff = (uint32_t)(wm * 32 + lrow) * ROWB + lcol;
    const uint32_t boff = ABYTES + (uint32_t)(wn * 48 + lrow) * ROWB + lcol;

    auto issue_load = [&](int c) {
        const __half* ap = (c < ncx) ? (xA + ((size_t)c * BATCH + m0) * KC)
                                     : (hA + ((size_t)(c - ncx) * BATCH + m0) * KC);
        const __half* bp = (c < ncx) ? (w1 + ((size_t)c * G3 + ub * NTILE) * KC)
                                     : (w2 + ((size_t)(c - ncx) * G3 + ub * NTILE) * KC);
        const char* asrc = (const char*)ap;
        const char* bsrc = (const char*)bp;
        uint32_t d = sb + 1024 + (uint32_t)(c & 1) * STAGE;
        // A: 128 rows x 320B = 2560 x 16B
#pragma unroll
        for (int i = 0; i < 10; ++i) {
            int u = tid + i * NTHR;
            cp16(d + (u / 20) * ROWB + (u % 20) * 16, asrc + (size_t)u * 16);
        }
        // B: 96 rows x 320B = 1920 x 16B
#pragma unroll
        for (int i = 0; i < 8; ++i) {
            int u = tid + i * NTHR;
            if (u < 1920)
                cp16(d + ABYTES + (u / 20) * ROWB + (u % 20) * 16, bsrc + (size_t)u * 16);
        }
        CP_COMMIT();
    };

    issue_load(0);

#define CHUNK_BODY(SPLIT)                                                       \
    {                                                                           \
        _Pragma("unroll")                                                       \
        for (int kk = 0; kk < 10; ++kk) {                                       \
            uint32_t a0[4], a1[4], b0[4], b1[4], b2[4];                         \
            ldm4(a0, stage + aoff + kk * 32);                                   \
            ldm4(a1, stage + aoff + 16 * ROWB + kk * 32);                       \
            ldm4(b0, stage + boff + kk * 32);                                   \
            ldm4(b1, stage + boff + 16 * ROWB + kk * 32);                       \
            ldm4(b2, stage + boff + 32 * ROWB + kk * 32);                       \
            mma_f16(acc[0][0], a0, b0[0], b0[2]);                               \
            mma_f16(acc[1][0], a1, b0[0], b0[2]);                               \
            mma_f16(acc[0][1], a0, b0[1], b0[3]);                               \
            mma_f16(acc[1][1], a1, b0[1], b0[3]);                               \
            if (SPLIT) {                                                        \
                mma_f16(accn[0][0], a0, b1[0], b1[2]);                          \
                mma_f16(accn[1][0], a1, b1[0], b1[2]);                          \
                mma_f16(accn[0][1], a0, b1[1], b1[3]);                          \
                mma_f16(accn[1][1], a1, b1[1], b1[3]);                          \
                mma_f16(accn[0][2], a0, b2[0], b2[2]);                          \
                mma_f16(accn[1][2], a1, b2[0], b2[2]);                          \
                mma_f16(accn[0][3], a0, b2[1], b2[3]);                          \
                mma_f16(accn[1][3], a1, b2[1], b2[3]);                          \
            } else {                                                            \
                mma_f16(acc[0][2], a0, b1[0], b1[2]);                           \
                mma_f16(acc[1][2], a1, b1[0], b1[2]);                           \
                mma_f16(acc[0][3], a0, b1[1], b1[3]);                           \
                mma_f16(acc[1][3], a1, b1[1], b1[3]);                           \
                mma_f16(acc[0][4], a0, b2[0], b2[2]);                           \
                mma_f16(acc[1][4], a1, b2[0], b2[2]);                           \
                mma_f16(acc[0][5], a0, b2[1], b2[3]);                           \
                mma_f16(acc[1][5], a1, b2[1], b2[3]);                           \
            }                                                                   \
        }                                                                       \
    }

    // 2-stage double buffer: wait(0) -> barrier -> issue(c+1) -> consume(c)
    for (int c = 0; c < nc; ++c) {
        CP_WAIT0();
        __syncthreads();
        if (c + 1 < nc) issue_load(c + 1);
        const uint32_t stage = sb + 1024 + (uint32_t)(c & 1) * STAGE;
        if (c >= ncx && wn == 1) CHUNK_BODY(1) else CHUNK_BODY(0)
    }
#undef CHUNK_BODY
    __syncthreads();   // ring fully consumed before plane overwrite

    // ---------------- epilogue: accums -> smem planes -> gate math ----------------
    float* Mp = (float*)(smem + 1024);
    float* Np = (float*)(smem + 1024 + N2OFF);
    {
        const int rb = wm * 32 + (lane >> 2);
        const int cb = wn * 48 + (lane & 3) * 2;
#pragma unroll
        for (int m2 = 0; m2 < 2; ++m2) {
#pragma unroll
            for (int f = 0; f < 6; ++f) {
                int r = rb + m2 * 16;
                int cc = cb + f * 8;
                *(float2*)&Mp[r * MSTRIDE + cc]       = make_float2(acc[m2][f][0], acc[m2][f][1]);
                *(float2*)&Mp[(r + 8) * MSTRIDE + cc] = make_float2(acc[m2][f][2], acc[m2][f][3]);
            }
        }
        if (wn == 1) {
            const int cb2 = (lane & 3) * 2;
#pragma unroll
            for (int m2 = 0; m2 < 2; ++m2) {
#pragma unroll
                for (int f = 0; f < 4; ++f) {
                    int r = rb + m2 * 16;
                    int cc = cb2 + f * 8;
                    *(float2*)&Np[r * N2STRIDE + cc]       = make_float2(accn[m2][f][0], accn[m2][f][1]);
                    *(float2*)&Np[(r + 8) * N2STRIDE + cc] = make_float2(accn[m2][f][2], accn[m2][f][3]);
                }
            }
        }
    }
    __syncthreads();

    {
        const int row = tid >> 1;
        const int j0  = (tid & 1) * 16;
        const int brow = m0 + row;
        const int cj = ub / 5;             // A-plane chunk (160 = 5 unit-blocks)
        const int kb = (ub % 5) * 32;

        float hv[16];
#pragma unroll
        for (int v = 0; v < 8; ++v) {
            int j = j0 + v * 2;
            float2 R  = *(float2*)&Mp[row * MSTRIDE + j];
            float2 Z  = *(float2*)&Mp[row * MSTRIDE + 32 + j];
            float2 NX = *(float2*)&Mp[row * MSTRIDE + 64 + j];
            float2 NH = *(float2*)&Np[row * N2STRIDE + j];
            float2 HP = *(const float2*)(hprevf + (size_t)brow * H + ub * 32 + j);
#pragma unroll
            for (int e = 0; e < 2; ++e) {
                int jj = j + e;
                float rr = sigf(((e ? R.y : R.x))  + sbias[jj]      + sbias[96 + jj]);
                float zz = sigf(((e ? Z.y : Z.x))  + sbias[32 + jj] + sbias[128 + jj]);
                float nn = tanhf(((e ? NX.y : NX.x)) + sbias[64 + jj]
                                 + rr * (((e ? NH.y : NH.x)) + sbias[160 + jj]));
                hv[j - j0 + e] = (1.0f - zz) * nn + zz * (e ? HP.y : HP.x);
            }
        }
        const size_t ob = (size_t)brow * H + ub * 32 + j0;
#pragma unroll
        for (int q = 0; q < 4; ++q)
            *(float4*)(houtf + ob + q * 4) = make_float4(hv[q*4], hv[q*4+1], hv[q*4+2], hv[q*4+3]);
        if (hcat) {
            const size_t cbo = (size_t)brow * hcat_ld + ub * 32 + j0;
#pragma unroll
            for (int q = 0; q < 4; ++q)
                *(float4*)(hcat + cbo + q * 4) = make_float4(hv[q*4], hv[q*4+1], hv[q*4+2], hv[q*4+3]);
        }
        // fp16 A-plane for next step
        __half hh[16];
#pragma unroll
        for (int i = 0; i < 16; ++i) hh[i] = __float2half_rn(hv[i]);
        const size_t so = ((size_t)cj * BATCH + brow) * KC + kb + j0;
        *(uint4*)(hAout + so)     = ((uint4*)hh)[0];
        *(uint4*)(hAout + so + 8) = ((uint4*)hh)[1];
    }
}

// ---------------- linear head ----------------
__global__ __launch_bounds__(256)
void linear_kernel(const float* __restrict__ h,
                   const float* __restrict__ W, const float* __restrict__ bias,
                   float* __restrict__ out, int out_ld,
                   __half* __restrict__ xdA)
{
    __shared__ float Ws[64][33];
    __shared__ float hs[8][64];
    const int tid = threadIdx.x;
    const int o = tid & 31;
    const int bl = tid >> 5;
    const int b0 = blockIdx.x * 8;

    float acc = 0.f;
    for (int k0 = 0; k0 < H; k0 += 64) {
#pragma unroll
        for (int i = 0; i < 8; ++i) {
            int idx = tid + i * 256;
            Ws[idx & 63][idx >> 6] = W[(size_t)(idx >> 6) * H + k0 + (idx & 63)];
        }
#pragma unroll
        for (int i = 0; i < 2; ++i) {
            int idx = tid + i * 256;
            hs[idx >> 6][idx & 63] = h[(size_t)(b0 + (idx >> 6)) * H + k0 + (idx & 63)];
        }
        __syncthreads();
#pragma unroll
        for (int kk = 0; kk < 64; ++kk)
            acc = fmaf(hs[bl][kk], Ws[kk][o], acc);
        __syncthreads();
    }
    float v = acc + bias[o];
    int b = b0 + bl;
    out[(size_t)b * out_ld + o] = v;
    xdA[(size_t)b * KC + o] = __float2half_rn(v);
}

// ---------------- prep kernels ----------------
__global__ void prep_weight_big(const float* __restrict__ W, __half* __restrict__ Wt)
{
    int total = G3 * NCH * KC;
    for (int idx = blockIdx.x * blockDim.x + threadIdx.x; idx < total; idx += gridDim.x * blockDim.x) {
        int k = idx % KC;
        int q = idx / KC;
        int n = q % G3;
        int c = q / G3;
        int ubl = n / 96, rem = n % 96, g = rem >> 5, jj = rem & 31;
        int row = g * H + ubl * 32 + jj;
        int col = c * KC + k;
        Wt[idx] = __float2half_rn(W[(size_t)row * H + col]);
    }
}

__global__ void prep_weight_sm(const float* __restrict__ W, int K, __half* __restrict__ Wt)
{
    int total = G3 * KC;
    for (int idx = blockIdx.x * blockDim.x + threadIdx.x; idx < total; idx += gridDim.x * blockDim.x) {
        int k = idx % KC;
        int n = idx / KC;
        int ubl = n / 96, rem = n % 96, g = rem >> 5, jj = rem & 31;
        int row = g * H + ubl * 32 + jj;
        float v = (k < K) ? W[(size_t)row * K + k] : 0.f;
        Wt[idx] = __float2half_rn(v);
    }
}

__global__ void prep_in(const float* __restrict__ in_data, __half* __restrict__ A)
{
    int total = T_IN * BATCH * KC;
    for (int idx = blockIdx.x * blockDim.x + threadIdx.x; idx < total; idx += gridDim.x * blockDim.x) {
        int k = idx % KC;
        int q = idx / KC;
        int b = q & (BATCH - 1);
        int t = q >> 9;
        float v = (k < IN_DIM) ? in_data[((size_t)b * T_IN + t) * IN_DIM + k] : 0.f;
        A[idx] = __float2half_rn(v);
    }
}

__global__ void prep_ll(const float* __restrict__ ll_src, __half* __restrict__ A)
{
    int total = BATCH * KC;
    for (int idx = blockIdx.x * blockDim.x + threadIdx.x; idx < total; idx += gridDim.x * blockDim.x) {
        int k = idx % KC;
        int b = idx / KC;
        float v = (k < HS) ? ll_src[(size_t)b * HS + k] : 0.f;
        A[idx] = __float2half_rn(v);
    }
}

// ---------------- host ----------------
extern "C" void kernel_launch(void* const* d_in, const int* in_sizes, int n_in,
                              void* d_out, int out_size)
{
    const float* in_data  = (const float*)d_in[0];
    const float* last_loc = (const float*)d_in[1];
    const float* eWih0 = (const float*)d_in[3];
    const float* eWhh0 = (const float*)d_in[4];
    const float* ebih0 = (const float*)d_in[5];
    const float* ebhh0 = (const float*)d_in[6];
    const float* eWih1 = (const float*)d_in[7];
    const float* eWhh1 = (const float*)d_in[8];
    const float* ebih1 = (const float*)d_in[9];
    const float* ebhh1 = (const float*)d_in[10];
    const float* dWih0 = (const float*)d_in[11];
    const float* dWhh0 = (const float*)d_in[12];
    const float* dbih0 = (const float*)d_in[13];
    const float* dbhh0 = (const float*)d_in[14];
    const float* dWih1 = (const float*)d_in[15];
    const float* dWhh1 = (const float*)d_in[16];
    const float* dbih1 = (const float*)d_in[17];
    const float* dbhh1 = (const float*)d_in[18];
    const float* linW  = (const float*)d_in[19];
    const float* linb  = (const float*)d_in[20];

    float* outputs = (float*)d_out;
    float* hidden  = (float*)d_out + (size_t)BATCH * T_PRED * OUT_DIM;

    __half (*Wb)[WBIG];         cudaGetSymbolAddress((void**)&Wb, g_W);
    __half (*Wsm)[WSM];         cudaGetSymbolAddress((void**)&Wsm, g_Wsm);
    float (*h0f)[BATCH * H];    cudaGetSymbolAddress((void**)&h0f, g_h0f);
    float (*h1f)[BATCH * H];    cudaGetSymbolAddress((void**)&h1f, g_h1f);
    __half (*h0a)[HSN];         cudaGetSymbolAddress((void**)&h0a, g_h0a);
    __half (*h1a)[HSN];         cudaGetSymbolAddress((void**)&h1a, g_h1a);
    __half* xin = nullptr;      cudaGetSymbolAddress((void**)&xin, g_xin);
    __half* xll = nullptr;      cudaGetSymbolAddress((void**)&xll, g_ll);
    __half* xd  = nullptr;      cudaGetSymbolAddress((void**)&xd, g_xd);

    cudaFuncSetAttribute(gru_step_h, cudaFuncAttributeMaxDynamicSharedMemorySize, SMEM_BYTES);

    prep_weight_big<<<1024, 256>>>(eWhh0, Wb[0]);
    prep_weight_big<<<1024, 256>>>(eWih1, Wb[1]);
    prep_weight_big<<<1024, 256>>>(eWhh1, Wb[2]);
    prep_weight_big<<<1024, 256>>>(dWhh0, Wb[3]);
    prep_weight_big<<<1024, 256>>>(dWih1, Wb[4]);
    prep_weight_big<<<1024, 256>>>(dWhh1, Wb[5]);
    prep_weight_sm<<<512, 256>>>(eWih0, IN_DIM, Wsm[0]);
    prep_weight_sm<<<512, 256>>>(dWih0, HS,     Wsm[1]);
    prep_in<<<1024, 256>>>(in_data, xin);
    prep_ll<<<128, 256>>>(last_loc, xll);

    cudaMemsetAsync(h0f[0], 0, (size_t)BATCH * H * sizeof(float));
    cudaMemsetAsync(h1f[0], 0, (size_t)BATCH * H * sizeof(float));
    cudaMemsetAsync(h0a[0], 0, (size_t)HSN * sizeof(__half));
    cudaMemsetAsync(h1a[0], 0, (size_t)HSN * sizeof(__half));
    cudaMemsetAsync(xd,     0, (size_t)BATCH * KC * sizeof(__half));

    dim3 grid(BATCH / MTILE, H / 32);   // (4, 30)
    int p0 = 0, p1 = 0;
    const int out_ld = T_PRED * OUT_DIM;
    const int hid_ld = T_PRED * 2 * H;

    // ---- encoder ----
    for (int t = 0; t < T_IN; ++t) {
        gru_step_h<<<grid, NTHR, SMEM_BYTES>>>(
            xin + (size_t)t * BATCH * KC, 1,
            h0a[p0], Wsm[0], Wb[0],
            ebih0, ebhh0, h0f[p0], h0f[1 - p0], h0a[1 - p0],
            nullptr, 0);
        p0 ^= 1;
        gru_step_h<<<grid, NTHR, SMEM_BYTES>>>(
            h0a[p0], NCH,
            h1a[p1], Wb[1], Wb[2],
            ebih1, ebhh1, h1f[p1], h1f[1 - p1], h1a[1 - p1],
            nullptr, 0);
        p1 ^= 1;
    }

    // ---- decoder ----
    for (int t = 0; t < T_PRED; ++t) {
        const __half* xAp = (t == 0) ? xll : xd;
        gru_step_h<<<grid, NTHR, SMEM_BYTES>>>(
            xAp, 1,
            h0a[p0], Wsm[1], Wb[3],
            dbih0, dbhh0, h0f[p0], h0f[1 - p0], h0a[1 - p0],
            hidden + (size_t)t * 2 * H, hid_ld);
        p0 ^= 1;
        gru_step_h<<<grid, NTHR, SMEM_BYTES>>>(
            h0a[p0], NCH,
            h1a[p1], Wb[4], Wb[5],
            dbih1, dbhh1, h1f[p1], h1f[1 - p1], h1a[1 - p1],
            hidden + (size_t)t * 2 * H + H, hid_ld);
        p1 ^= 1;
        linear_kernel<<<BATCH / 8, 256>>>(h1f[p1], linW, linb,
                                          outputs + (size_t)t * OUT_DIM, out_ld, xd);
    }
}